// round 16
// baseline (speedup 1.0000x reference)
#include <cuda_runtime.h>
#include <math.h>
#include <stdint.h>

#define Tdim 4096
#define Hdim 4096
#define Idim 11008
#define NW ((size_t)Idim*(size_t)Hdim)
#define NCH_H 32            // Hdim/128
#define NCH_I 86            // Idim/128

// ---- static device scratch ----
// A blobs (16KB per (mtile128, chunk)): kmaj swz rows 0..127; At blobs [kw32][128 words].
// B blobs (8KB per (ntile64, chunk)): [0,4K) cols0..31 kmaj swz; [4K,8K) cols32..63 transposed [kw32][32w]
__device__ __align__(16) signed char g_wqg[NW];
__device__ __align__(16) signed char g_wqu[NW];
__device__ __align__(16) signed char g_wqd[NW];
__device__ __align__(16) signed char g_xq [(size_t)Tdim*Hdim];
__device__ __align__(16) signed char g_xqt[(size_t)Tdim*Hdim];
__device__ __align__(16) signed char g_hq [(size_t)Tdim*Idim];
__device__ __align__(16) signed char g_hqt[(size_t)Tdim*Idim];
__device__ float g_gbuf[(size_t)Tdim*Idim];
__device__ float g_ainv[Tdim];
__device__ float g_hinv[Tdim];
__device__ float g_partial[3][2048];
__device__ float g_wscale[3];
__device__ float g_winv[3];
__device__ unsigned g_cnt = 0;

// ======================= PTX helpers =======================
__device__ __forceinline__ uint32_t smem_u32(const void* p) {
    uint32_t a;
    asm("{ .reg .u64 t; cvta.to.shared.u64 t, %1; cvt.u32.u64 %0, t; }" : "=r"(a) : "l"(p));
    return a;
}
#define MBAR_INIT(a, c) asm volatile("mbarrier.init.shared.b64 [%0], %1;" :: "r"(a), "r"(c) : "memory")
#define MBAR_EXPECT(a, b) asm volatile("mbarrier.arrive.expect_tx.shared.b64 _, [%0], %1;" :: "r"(a), "r"(b) : "memory")
__device__ __forceinline__ void mbar_wait(uint32_t addr, uint32_t parity) {
    asm volatile(
        "{\n\t.reg .pred P;\n\t"
        "LW_%=:\n\t"
        "mbarrier.try_wait.parity.acquire.cta.shared::cta.b64 P, [%0], %1, 0x989680;\n\t"
        "@P bra.uni LD_%=;\n\t"
        "bra.uni LW_%=;\n\t"
        "LD_%=:\n\t}"
        :: "r"(addr), "r"(parity) : "memory");
}
__device__ __forceinline__ void bulk_g2s(uint32_t dst, const void* src, uint32_t bytes, uint32_t mbar) {
    asm volatile("cp.async.bulk.shared::cluster.global.mbarrier::complete_tx::bytes [%0], [%1], %2, [%3];"
        :: "r"(dst), "l"(src), "r"(bytes), "r"(mbar) : "memory");
}
#define LDSM4(r, a) asm volatile( \
    "ldmatrix.sync.aligned.m8n8.x4.shared.b16 {%0,%1,%2,%3}, [%4];" \
    : "=r"((r)[0]), "=r"((r)[1]), "=r"((r)[2]), "=r"((r)[3]) : "r"(a))
#define MMA_S8(d, a, b0, b1) asm volatile( \
    "mma.sync.aligned.m16n8k32.row.col.s32.s8.s8.s32 " \
    "{%0,%1,%2,%3}, {%4,%5,%6,%7}, {%8,%9}, {%0,%1,%2,%3};" \
    : "+r"((d)[0]), "+r"((d)[1]), "+r"((d)[2]), "+r"((d)[3]) \
    : "r"((a)[0]), "r"((a)[1]), "r"((a)[2]), "r"((a)[3]), "r"(b0), "r"(b1))
#define LDS128(v, a) asm volatile("ld.shared.v4.u32 {%0,%1,%2,%3}, [%4];" \
    : "=r"((v).x), "=r"((v).y), "=r"((v).z), "=r"((v).w) : "r"(a))

__device__ __forceinline__ int quant_word(float4 v, float sc, float lo, float hi) {
    int b0 = (int)fminf(hi, fmaxf(lo, rintf(v.x * sc)));
    int b1 = (int)fminf(hi, fmaxf(lo, rintf(v.y * sc)));
    int b2 = (int)fminf(hi, fmaxf(lo, rintf(v.z * sc)));
    int b3 = (int)fminf(hi, fmaxf(lo, rintf(v.w * sc)));
    return (b0 & 0xFF) | ((b1 & 0xFF) << 8) | ((b2 & 0xFF) << 16) | (b3 << 24);
}

// ======================= absmean + finalize (float4 loads) =======================
__global__ void absmean_all(const float* __restrict__ wg, const float* __restrict__ wu,
                            const float* __restrict__ wd, long n) {
    __shared__ float red[256];
    __shared__ double redd[256];
    __shared__ bool amLast;
    int which = blockIdx.y;
    const float* w = which == 0 ? wg : (which == 1 ? wu : wd);
    const float4* w4 = (const float4*)w;
    long n4 = n >> 2;
    float s = 0.f;
    long stride = (long)gridDim.x * blockDim.x;
    for (long i = (long)blockIdx.x * blockDim.x + threadIdx.x; i < n4; i += stride) {
        float4 v = w4[i];
        s += fabsf(v.x) + fabsf(v.y) + fabsf(v.z) + fabsf(v.w);
    }
    red[threadIdx.x] = s;
    __syncthreads();
    for (int o = 128; o > 0; o >>= 1) {
        if (threadIdx.x < o) red[threadIdx.x] += red[threadIdx.x + o];
        __syncthreads();
    }
    if (threadIdx.x == 0) {
        g_partial[which][blockIdx.x] = red[0];
        __threadfence();
        unsigned t = atomicAdd(&g_cnt, 1u);
        amLast = (t == gridDim.x * 3 - 1);
    }
    __syncthreads();
    if (amLast) {
        for (int m = 0; m < 3; m++) {
            double s2 = 0.0;
            for (int i = threadIdx.x; i < 2048; i += 256) s2 += (double)g_partial[m][i];
            redd[threadIdx.x] = s2;
            __syncthreads();
            for (int o = 128; o > 0; o >>= 1) {
                if (threadIdx.x < o) redd[threadIdx.x] += redd[threadIdx.x + o];
                __syncthreads();
            }
            if (threadIdx.x == 0) {
                float mean = (float)(redd[0] / (double)n);
                float cm = fmaxf(mean, 1e-5f);
                g_wscale[m] = 1.f / cm;
                g_winv[m] = cm;
            }
            __syncthreads();
        }
        if (threadIdx.x == 0) g_cnt = 0;
    }
}

// ======================= weight quant -> 8KB B blobs per (ntile64, chunk) ===========
__global__ void quant_weight_all(const float* __restrict__ wg, const float* __restrict__ wu,
                                 const float* __restrict__ wd) {
    __shared__ int s[32][133];
    int which = blockIdx.y;
    const float* w; signed char* outb; int Kf, ktc;
    if (which == 0)      { w = wg; outb = g_wqg; Kf = Hdim; ktc = NCH_H; }
    else if (which == 1) { w = wu; outb = g_wqu; Kf = Hdim; ktc = NCH_H; }
    else                 { w = wd; outb = g_wqd; Kf = Idim; ktc = NCH_I; }
    int bx = blockIdx.x;
    int kc = bx % ktc, nt128 = bx / ktc;
    int kc0 = kc * 128, n0 = nt128 * 128;
    float sw = g_wscale[which];
    int t = threadIdx.x;
    int r = t >> 1, h = t & 1;
    const float* wr = w + (size_t)(n0 + r) * Kf + kc0 + h * 64;
    int words[16];
#pragma unroll
    for (int q = 0; q < 16; q++) {
        words[q] = quant_word(*(const float4*)(wr + q * 4), sw, -1.f, 1.f);
        s[h * 16 + q][r] = words[q];
    }
    if ((r & 63) < 32) {
        int nt64 = nt128 * 2 + (r >> 6);
        int rloc = r & 31;
        signed char* blob = outb + (((size_t)nt64 * ktc + kc) << 13);
#pragma unroll
        for (int qq = 0; qq < 4; qq++) {
            int c16 = h * 4 + qq;
            *(int4*)(blob + rloc * 128 + ((c16 ^ (rloc & 7)) << 4)) =
                make_int4(words[qq*4], words[qq*4+1], words[qq*4+2], words[qq*4+3]);
        }
    }
    __syncthreads();
    int kw = t >> 3, seg = t & 7;
    int nt64 = nt128 * 2 + (seg >> 2);
    int cseg = seg & 3;
    signed char* blob = outb + (((size_t)nt64 * ktc + kc) << 13);
    int srcbase = (seg >> 2) * 64 + 32 + cseg * 8;
    signed char* tp = blob + 4096 + kw * 128 + cseg * 32;
    *(int4*)tp = make_int4(s[kw][srcbase+0], s[kw][srcbase+1], s[kw][srcbase+2], s[kw][srcbase+3]);
    *(int4*)(tp+16) = make_int4(s[kw][srcbase+4], s[kw][srcbase+5], s[kw][srcbase+6], s[kw][srcbase+7]);
}

// ======================= act quant -> A blob (swz) + At blob (transposed) =======================
__global__ void quant_act_t(const float* __restrict__ x, signed char* __restrict__ xq,
                            signed char* __restrict__ xqt, float* __restrict__ ainv,
                            int Kf, int nch) {
    __shared__ float rscale[32];
    __shared__ float rinvs[32];
    __shared__ int s[32][33];
    int t = threadIdx.x, warp = t >> 5, lane = t & 31;
    int row0 = blockIdx.x * 32;
    int mt = row0 >> 7, rbase = row0 & 127;
#pragma unroll
    for (int rr = 0; rr < 4; rr++) {
        int r = warp * 4 + rr;
        const float4* xr = (const float4*)(x + (size_t)(row0 + r) * Kf);
        float mx = 0.f;
        for (int i = lane; i < Kf / 4; i += 32) {
            float4 v = xr[i];
            mx = fmaxf(mx, fmaxf(fmaxf(fabsf(v.x), fabsf(v.y)), fmaxf(fabsf(v.z), fabsf(v.w))));
        }
#pragma unroll
        for (int o = 16; o > 0; o >>= 1) mx = fmaxf(mx, __shfl_xor_sync(0xFFFFFFFFu, mx, o));
        if (lane == 0) {
            float cm = fmaxf(mx, 1e-5f);
            rscale[r] = 127.f / cm;
            rinvs[r] = cm * (1.f / 127.f);
        }
    }
    __syncthreads();
    if (t < 32) ainv[row0 + t] = rinvs[t];
    int r = t >> 3, seg = t & 7;
    int rloc = rbase + r;
    float sc = rscale[r];
    const float* xr = x + (size_t)(row0 + r) * Kf;
    for (int kt = 0; kt < nch; kt++) {
        size_t blob = ((size_t)(mt * nch + kt)) << 14;
        int words[4];
#pragma unroll
        for (int q = 0; q < 4; q++) {
            words[q] = quant_word(*(const float4*)(xr + kt * 128 + seg * 16 + q * 4), sc, -128.f, 127.f);
            s[seg * 4 + q][r] = words[q];
        }
        *(int4*)(xq + blob + rloc * 128 + ((seg ^ (rloc & 7)) << 4)) =
            make_int4(words[0], words[1], words[2], words[3]);
        __syncthreads();
#pragma unroll
        for (int q = 0; q < 4; q++) {
            int kw = q * 8 + warp;
            *(int*)(xqt + blob + kw * 512 + (rbase + lane) * 4) = s[kw][lane];
        }
        __syncthreads();
    }
}

// ======================= rmsnorm + act quant -> hq/hqt blobs =======================
__global__ void rmsnorm_quant(const float* __restrict__ h, const float* __restrict__ lnw,
                              signed char* __restrict__ hq, signed char* __restrict__ hqt,
                              float* __restrict__ hinv) {
    __shared__ float sh[Idim];
    __shared__ float red[256];
    int tid = threadIdx.x;
    int row = blockIdx.x;
    int mt = row >> 7, rloc = row & 127;
    long base = (long)row * Idim;
    float ss = 0.f;
    for (int i = tid; i < Idim; i += 256) {
        float v = h[base + i];
        sh[i] = v;
        ss += v * v;
    }
    red[tid] = ss;
    __syncthreads();
    for (int o = 128; o > 0; o >>= 1) {
        if (tid < o) red[tid] += red[tid + o];
        __syncthreads();
    }
    float rs = rsqrtf(red[0] / (float)Idim + 1e-6f);
    __syncthreads();
    float mx = 0.f;
    for (int i = tid; i < Idim; i += 256) {
        float hn = lnw[i] * sh[i] * rs;
        sh[i] = hn;
        mx = fmaxf(mx, fabsf(hn));
    }
    red[tid] = mx;
    __syncthreads();
    for (int o = 128; o > 0; o >>= 1) {
        if (tid < o) red[tid] = fmaxf(red[tid], red[tid + o]);
        __syncthreads();
    }
    float cm = fmaxf(red[0], 1e-5f);
    float s = 127.f / cm;
    if (tid == 0) hinv[row] = cm * (1.f / 127.f);
    __syncthreads();
    for (int g = tid; g < Idim / 16; g += 256) {
        int kt = g >> 3, c16 = g & 7;
        size_t blob = ((size_t)(mt * NCH_I + kt)) << 14;
        int w[4];
#pragma unroll
        for (int qi = 0; qi < 4; qi++) {
            const float* p = sh + g * 16 + qi * 4;
            w[qi] = quant_word(make_float4(p[0], p[1], p[2], p[3]), s, -128.f, 127.f);
            *(int*)(hqt + blob + (c16 * 4 + qi) * 512 + rloc * 4) = w[qi];
        }
        *(int4*)(hq + blob + rloc * 128 + ((c16 ^ (rloc & 7)) << 4)) =
            make_int4(w[0], w[1], w[2], w[3]);
    }
}

// ======== hybrid GEMM: 128x64 tile, 2 CTAs/SM, HOMOGENEOUS warps (MMA+dp4a interleaved) ====
// Each of 8 warps owns M rows [w*16, w*16+16): MMA on cols [0,32), dp4a on cols [32,64).
// Per s-step: issue m16 MMAs (tensor pipe works in background), then dp4a block kw=s*8..s*8+7.
template<int NB, int STAGES>
__global__ void __launch_bounds__(256, 2)
gemm_hyb(const signed char* __restrict__ A, const signed char* __restrict__ At,
         const signed char* __restrict__ B0, const signed char* __restrict__ B1,
         float* __restrict__ C, int NC, int Nout,
         const float* __restrict__ rowinv, int iw0, int iw1)
{
    extern __shared__ char smem[];
    char* sp = (char*)(((uintptr_t)smem + 1023u) & ~(uintptr_t)1023u);
    const uint32_t db = smem_u32(sp);
    constexpr uint32_t STAGE_B = (NB == 2) ? 49152u : 40960u;
    const uint32_t mb = db + STAGES * STAGE_B;
    const int tid = threadIdx.x, lane = tid & 31, wid = tid >> 5;
    const int m0 = blockIdx.x * 128, n0 = blockIdx.y * 64;

    if (tid == 0)
        for (int s = 0; s < STAGES; s++) MBAR_INIT(mb + s * 8, 1);
    __syncthreads();

    const size_t blobA = ((size_t)blockIdx.x * NC) << 14;
    const size_t blobB = ((size_t)blockIdx.y * NC) << 13;

    auto issue = [&](int chunk) {
        if (tid != 0) return;
        int st = chunk % STAGES;
        uint32_t bar = mb + st * 8;
        uint32_t base = db + st * STAGE_B;
        MBAR_EXPECT(bar, STAGE_B);
        bulk_g2s(base,          A  + blobA + ((size_t)chunk << 14), 16384, bar);
        bulk_g2s(base + 16384,  At + blobA + ((size_t)chunk << 14), 16384, bar);
        bulk_g2s(base + 32768,  B0 + blobB + ((size_t)chunk << 13), 8192, bar);
        if (NB == 2) bulk_g2s(base + 40960, B1 + blobB + ((size_t)chunk << 13), 8192, bar);
    };

    auto swz = [](int row, int c16) -> uint32_t {
        return (uint32_t)(row * 128 + ((c16 ^ (row & 7)) << 4));
    };

    // MMA state: warp owns m16 tile at rows wid*16
    const int mrow = wid * 16 + (lane & 15);
    const int acol = (lane >> 4);
    const int brow = (lane & 7) + ((lane & 16) ? 8 : 0);
    const int bcol = ((lane >> 3) & 1);
    int acc[NB][4][4];
#pragma unroll
    for (int b = 0; b < NB; b++)
#pragma unroll
        for (int n8 = 0; n8 < 4; n8++)
#pragma unroll
            for (int q = 0; q < 4; q++) acc[b][n8][q] = 0;

    // dp4a state: warp rows wid*16 + (lane>>3)*4 (4 rows), cols 32 + (lane&7)*4
    const int drow = wid * 16 + ((lane >> 3) << 2);
    const int dcol = (lane & 7) << 2;
    int dac0[4][4], dac1[4][4];
#pragma unroll
    for (int i = 0; i < 4; i++)
#pragma unroll
        for (int j = 0; j < 4; j++) { dac0[i][j] = 0; if (NB == 2) dac1[i][j] = 0; }

    int fill = 0;
    for (; fill < STAGES - 1 && fill < NC; fill++) issue(fill);

    for (int ch = 0; ch < NC; ch++) {
        if (fill < NC) { issue(fill); fill++; }
        int st = ch % STAGES;
        mbar_wait(mb + st * 8, (ch / STAGES) & 1);

        uint32_t sboff = (uint32_t)st * STAGE_B;
        uint32_t abase = db + sboff;
        uint32_t atb  = abase + 16384u + (uint32_t)(drow * 4);
        uint32_t bt0  = abase + 32768u + 4096u + (uint32_t)(dcol * 4);
        uint32_t bt1  = abase + 40960u + 4096u + (uint32_t)(dcol * 4);

#pragma unroll
        for (int s = 0; s < 4; s++) {
            // ---- MMA phase for K-step s (sinks into tensor queue) ----
            uint32_t af[4];
            LDSM4(af, abase + swz(mrow, s * 2 + acol));
#pragma unroll
            for (int b = 0; b < NB; b++) {
                uint32_t bb = abase + 32768u + (uint32_t)b * 8192u;
#pragma unroll
                for (int nt = 0; nt < 2; nt++) {
                    uint32_t bf[4];
                    int row = nt * 16 + brow;
                    LDSM4(bf, bb + swz(row, s * 2 + bcol));
                    MMA_S8(acc[b][nt * 2 + 0], af, bf[0], bf[1]);
                    MMA_S8(acc[b][nt * 2 + 1], af, bf[2], bf[3]);
                }
            }
            // ---- dp4a phase kw = s*8 .. s*8+7 (fma pipe, overlaps tensor drain) ----
#pragma unroll
            for (int q = 0; q < 8; q++) {
                int kk = s * 8 + q;
                int4 av, bv0;
                LDS128(av, atb + kk * 512);
                LDS128(bv0, bt0 + kk * 128);
                int a[4] = {av.x, av.y, av.z, av.w};
                int b0w[4] = {bv0.x, bv0.y, bv0.z, bv0.w};
#pragma unroll
                for (int i = 0; i < 4; i++)
#pragma unroll
                    for (int j = 0; j < 4; j++)
                        dac0[i][j] = __dp4a(a[i], b0w[j], dac0[i][j]);
                if (NB == 2) {
                    int4 bv1;
                    LDS128(bv1, bt1 + kk * 128);
                    int b1w[4] = {bv1.x, bv1.y, bv1.z, bv1.w};
#pragma unroll
                    for (int i = 0; i < 4; i++)
#pragma unroll
                        for (int j = 0; j < 4; j++)
                            dac1[i][j] = __dp4a(a[i], b1w[j], dac1[i][j]);
                }
            }
        }
        __syncthreads();
    }

    // ======== epilogue ========
    float wg0 = g_winv[iw0], wu0 = (NB == 2) ? g_winv[iw1] : 0.f;
    // MMA half: cols [0,32)
    {
        int r = m0 + wid * 16 + (lane >> 2);        // rows r, r+8
        float ai0 = rowinv[r], ai1 = rowinv[r + 8];
        float* crow0 = C + (size_t)r * Nout;
        float* crow1 = C + (size_t)(r + 8) * Nout;
        if (NB == 2) {
            float sg0 = ai0 * wg0, su0 = ai0 * wu0;
            float sg1 = ai1 * wg0, su1 = ai1 * wu0;
#pragma unroll
            for (int n8 = 0; n8 < 4; n8++) {
                int c = n0 + n8 * 8 + (lane & 3) * 2;
                float g00 = (float)acc[0][n8][0] * sg0;
                float g01 = (float)acc[0][n8][1] * sg0;
                float g10 = (float)acc[0][n8][2] * sg1;
                float g11 = (float)acc[0][n8][3] * sg1;
                float u00 = (float)acc[1][n8][0] * su0;
                float u01 = (float)acc[1][n8][1] * su0;
                float u10 = (float)acc[1][n8][2] * su1;
                float u11 = (float)acc[1][n8][3] * su1;
                float2 o0, o1;
                o0.x = (g00 / (1.f + expf(-g00))) * u00;
                o0.y = (g01 / (1.f + expf(-g01))) * u01;
                o1.x = (g10 / (1.f + expf(-g10))) * u10;
                o1.y = (g11 / (1.f + expf(-g11))) * u11;
                *(float2*)(crow0 + c) = o0;
                *(float2*)(crow1 + c) = o1;
            }
        } else {
            float s0 = ai0 * wg0, s1 = ai1 * wg0;
#pragma unroll
            for (int n8 = 0; n8 < 4; n8++) {
                int c = n0 + n8 * 8 + (lane & 3) * 2;
                float2 o0, o1;
                o0.x = (float)acc[0][n8][0] * s0;
                o0.y = (float)acc[0][n8][1] * s0;
                o1.x = (float)acc[0][n8][2] * s1;
                o1.y = (float)acc[0][n8][3] * s1;
                *(float2*)(crow0 + c) = o0;
                *(float2*)(crow1 + c) = o1;
            }
        }
    }
    // dp4a half: cols [32,64)
    {
        int cbase = n0 + 32 + dcol;
#pragma unroll
        for (int i = 0; i < 4; i++) {
            int r = m0 + drow + i;
            float ai = rowinv[r];
            float* crow = C + (size_t)r * Nout + cbase;
            if (NB == 2) {
                float sg = ai * wg0, su = ai * wu0;
                float4 o;
                float g0 = (float)dac0[i][0] * sg, u0 = (float)dac1[i][0] * su;
                float g1 = (float)dac0[i][1] * sg, u1 = (float)dac1[i][1] * su;
                float g2 = (float)dac0[i][2] * sg, u2 = (float)dac1[i][2] * su;
                float g3 = (float)dac0[i][3] * sg, u3 = (float)dac1[i][3] * su;
                o.x = (g0 / (1.f + expf(-g0))) * u0;
                o.y = (g1 / (1.f + expf(-g1))) * u1;
                o.z = (g2 / (1.f + expf(-g2))) * u2;
                o.w = (g3 / (1.f + expf(-g3))) * u3;
                *(float4*)crow = o;
            } else {
                float sc = ai * wg0;
                float4 o;
                o.x = (float)dac0[i][0] * sc;
                o.y = (float)dac0[i][1] * sc;
                o.z = (float)dac0[i][2] * sc;
                o.w = (float)dac0[i][3] * sc;
                *(float4*)crow = o;
            }
        }
    }
}

// ======================= launch =======================
extern "C" void kernel_launch(void* const* d_in, const int* in_sizes, int n_in,
                              void* d_out, int out_size) {
    const float* x   = (const float*)d_in[0];
    const float* wg  = (const float*)d_in[1];
    const float* wu  = (const float*)d_in[2];
    const float* wd  = (const float*)d_in[3];
    const float* lnw = (const float*)d_in[4];
    float* out = (float*)d_out;

    signed char *wqg, *wqu, *wqd, *xq, *xqt, *hq, *hqt;
    float *gbuf, *ainv, *hinv;
    cudaGetSymbolAddress((void**)&wqg, g_wqg);
    cudaGetSymbolAddress((void**)&wqu, g_wqu);
    cudaGetSymbolAddress((void**)&wqd, g_wqd);
    cudaGetSymbolAddress((void**)&xq, g_xq);
    cudaGetSymbolAddress((void**)&xqt, g_xqt);
    cudaGetSymbolAddress((void**)&hq, g_hq);
    cudaGetSymbolAddress((void**)&hqt, g_hqt);
    cudaGetSymbolAddress((void**)&gbuf, g_gbuf);
    cudaGetSymbolAddress((void**)&ainv, g_ainv);
    cudaGetSymbolAddress((void**)&hinv, g_hinv);

    const int SMEM2 = 2 * 49152 + 1024 + 64;   // 2 CTAs/SM
    const int SMEM1 = 2 * 40960 + 1024 + 64;   // 2 CTAs/SM
    cudaFuncSetAttribute(gemm_hyb<2, 2>, cudaFuncAttributeMaxDynamicSharedMemorySize, SMEM2);
    cudaFuncSetAttribute(gemm_hyb<1, 2>, cudaFuncAttributeMaxDynamicSharedMemorySize, SMEM1);

    const long NWl = (long)NW;

    absmean_all<<<dim3(2048, 3), 256>>>(wg, wu, wd, NWl);
    quant_weight_all<<<dim3(2752, 3), 256>>>(wg, wu, wd);
    quant_act_t<<<Tdim / 32, 256>>>(x, xq, xqt, ainv, Hdim, NCH_H);
    // ncu slot: fused gate+up hybrid GEMM -> h = silu(g)*u
    gemm_hyb<2, 2><<<dim3(Tdim / 128, Idim / 64), 256, SMEM2>>>(
        xq, xqt, wqg, wqu, gbuf, NCH_H, Idim, ainv, 0, 1);
    rmsnorm_quant<<<Tdim, 256>>>(gbuf, lnw, hq, hqt, hinv);
    gemm_hyb<1, 2><<<dim3(Tdim / 128, Hdim / 64), 256, SMEM1>>>(
        hq, hqt, wqd, wqd, out, NCH_I, Hdim, hinv, 2, 2);
}

// round 17
// speedup vs baseline: 1.1714x; 1.1714x over previous
#include <cuda_runtime.h>
#include <math.h>
#include <stdint.h>

#define Tdim 4096
#define Hdim 4096
#define Idim 11008
#define NW ((size_t)Idim*(size_t)Hdim)
#define NCH_H 32            // Hdim/128
#define NCH_I 86            // Idim/128

// ---- static device scratch ----
// A blobs (16KB per (mtile128, chunk)): kmaj swz rows 0..127; At blobs [kw32][128 words].
// B blobs (8KB per (ntile64, chunk)): [0,4K) cols0..31 kmaj swz; [4K,8K) cols32..63 transposed [kw32][32w]
__device__ __align__(16) signed char g_wqg[NW];
__device__ __align__(16) signed char g_wqu[NW];
__device__ __align__(16) signed char g_wqd[NW];
__device__ __align__(16) signed char g_xq [(size_t)Tdim*Hdim];
__device__ __align__(16) signed char g_xqt[(size_t)Tdim*Hdim];
__device__ __align__(16) signed char g_hq [(size_t)Tdim*Idim];
__device__ __align__(16) signed char g_hqt[(size_t)Tdim*Idim];
__device__ float g_gbuf[(size_t)Tdim*Idim];
__device__ float g_ainv[Tdim];
__device__ float g_hinv[Tdim];
__device__ float g_partial[3][2048];
__device__ float g_wscale[3];
__device__ float g_winv[3];
__device__ unsigned g_cnt = 0;

// ======================= PTX helpers =======================
__device__ __forceinline__ uint32_t smem_u32(const void* p) {
    uint32_t a;
    asm("{ .reg .u64 t; cvta.to.shared.u64 t, %1; cvt.u32.u64 %0, t; }" : "=r"(a) : "l"(p));
    return a;
}
#define MBAR_INIT(a, c) asm volatile("mbarrier.init.shared.b64 [%0], %1;" :: "r"(a), "r"(c) : "memory")
#define MBAR_EXPECT(a, b) asm volatile("mbarrier.arrive.expect_tx.shared.b64 _, [%0], %1;" :: "r"(a), "r"(b) : "memory")
__device__ __forceinline__ void mbar_wait(uint32_t addr, uint32_t parity) {
    asm volatile(
        "{\n\t.reg .pred P;\n\t"
        "LW_%=:\n\t"
        "mbarrier.try_wait.parity.acquire.cta.shared::cta.b64 P, [%0], %1, 0x989680;\n\t"
        "@P bra.uni LD_%=;\n\t"
        "bra.uni LW_%=;\n\t"
        "LD_%=:\n\t}"
        :: "r"(addr), "r"(parity) : "memory");
}
__device__ __forceinline__ void bulk_g2s(uint32_t dst, const void* src, uint32_t bytes, uint32_t mbar) {
    asm volatile("cp.async.bulk.shared::cluster.global.mbarrier::complete_tx::bytes [%0], [%1], %2, [%3];"
        :: "r"(dst), "l"(src), "r"(bytes), "r"(mbar) : "memory");
}
#define LDSM4(r, a) asm volatile( \
    "ldmatrix.sync.aligned.m8n8.x4.shared.b16 {%0,%1,%2,%3}, [%4];" \
    : "=r"((r)[0]), "=r"((r)[1]), "=r"((r)[2]), "=r"((r)[3]) : "r"(a))
#define MMA_S8(d, a, b0, b1) asm volatile( \
    "mma.sync.aligned.m16n8k32.row.col.s32.s8.s8.s32 " \
    "{%0,%1,%2,%3}, {%4,%5,%6,%7}, {%8,%9}, {%0,%1,%2,%3};" \
    : "+r"((d)[0]), "+r"((d)[1]), "+r"((d)[2]), "+r"((d)[3]) \
    : "r"((a)[0]), "r"((a)[1]), "r"((a)[2]), "r"((a)[3]), "r"(b0), "r"(b1))
#define LDS128(v, a) asm volatile("ld.shared.v4.u32 {%0,%1,%2,%3}, [%4];" \
    : "=r"((v).x), "=r"((v).y), "=r"((v).z), "=r"((v).w) : "r"(a))

__device__ __forceinline__ int quant_word(float4 v, float sc, float lo, float hi) {
    int b0 = (int)fminf(hi, fmaxf(lo, rintf(v.x * sc)));
    int b1 = (int)fminf(hi, fmaxf(lo, rintf(v.y * sc)));
    int b2 = (int)fminf(hi, fmaxf(lo, rintf(v.z * sc)));
    int b3 = (int)fminf(hi, fmaxf(lo, rintf(v.w * sc)));
    return (b0 & 0xFF) | ((b1 & 0xFF) << 8) | ((b2 & 0xFF) << 16) | (b3 << 24);
}

// ======================= absmean + finalize (float4 loads) =======================
__global__ void absmean_all(const float* __restrict__ wg, const float* __restrict__ wu,
                            const float* __restrict__ wd, long n) {
    __shared__ float red[256];
    __shared__ double redd[256];
    __shared__ bool amLast;
    int which = blockIdx.y;
    const float* w = which == 0 ? wg : (which == 1 ? wu : wd);
    const float4* w4 = (const float4*)w;
    long n4 = n >> 2;
    float s = 0.f;
    long stride = (long)gridDim.x * blockDim.x;
    for (long i = (long)blockIdx.x * blockDim.x + threadIdx.x; i < n4; i += stride) {
        float4 v = w4[i];
        s += fabsf(v.x) + fabsf(v.y) + fabsf(v.z) + fabsf(v.w);
    }
    red[threadIdx.x] = s;
    __syncthreads();
    for (int o = 128; o > 0; o >>= 1) {
        if (threadIdx.x < o) red[threadIdx.x] += red[threadIdx.x + o];
        __syncthreads();
    }
    if (threadIdx.x == 0) {
        g_partial[which][blockIdx.x] = red[0];
        __threadfence();
        unsigned t = atomicAdd(&g_cnt, 1u);
        amLast = (t == gridDim.x * 3 - 1);
    }
    __syncthreads();
    if (amLast) {
        for (int m = 0; m < 3; m++) {
            double s2 = 0.0;
            for (int i = threadIdx.x; i < 2048; i += 256) s2 += (double)g_partial[m][i];
            redd[threadIdx.x] = s2;
            __syncthreads();
            for (int o = 128; o > 0; o >>= 1) {
                if (threadIdx.x < o) redd[threadIdx.x] += redd[threadIdx.x + o];
                __syncthreads();
            }
            if (threadIdx.x == 0) {
                float mean = (float)(redd[0] / (double)n);
                float cm = fmaxf(mean, 1e-5f);
                g_wscale[m] = 1.f / cm;
                g_winv[m] = cm;
            }
            __syncthreads();
        }
        if (threadIdx.x == 0) g_cnt = 0;
    }
}

// ======================= weight quant -> 8KB B blobs per (ntile64, chunk) ===========
__global__ void quant_weight_all(const float* __restrict__ wg, const float* __restrict__ wu,
                                 const float* __restrict__ wd) {
    __shared__ int s[32][133];
    int which = blockIdx.y;
    const float* w; signed char* outb; int Kf, ktc;
    if (which == 0)      { w = wg; outb = g_wqg; Kf = Hdim; ktc = NCH_H; }
    else if (which == 1) { w = wu; outb = g_wqu; Kf = Hdim; ktc = NCH_H; }
    else                 { w = wd; outb = g_wqd; Kf = Idim; ktc = NCH_I; }
    int bx = blockIdx.x;
    int kc = bx % ktc, nt128 = bx / ktc;
    int kc0 = kc * 128, n0 = nt128 * 128;
    float sw = g_wscale[which];
    int t = threadIdx.x;
    int r = t >> 1, h = t & 1;
    const float* wr = w + (size_t)(n0 + r) * Kf + kc0 + h * 64;
    int words[16];
#pragma unroll
    for (int q = 0; q < 16; q++) {
        words[q] = quant_word(*(const float4*)(wr + q * 4), sw, -1.f, 1.f);
        s[h * 16 + q][r] = words[q];
    }
    if ((r & 63) < 32) {
        int nt64 = nt128 * 2 + (r >> 6);
        int rloc = r & 31;
        signed char* blob = outb + (((size_t)nt64 * ktc + kc) << 13);
#pragma unroll
        for (int qq = 0; qq < 4; qq++) {
            int c16 = h * 4 + qq;
            *(int4*)(blob + rloc * 128 + ((c16 ^ (rloc & 7)) << 4)) =
                make_int4(words[qq*4], words[qq*4+1], words[qq*4+2], words[qq*4+3]);
        }
    }
    __syncthreads();
    int kw = t >> 3, seg = t & 7;
    int nt64 = nt128 * 2 + (seg >> 2);
    int cseg = seg & 3;
    signed char* blob = outb + (((size_t)nt64 * ktc + kc) << 13);
    int srcbase = (seg >> 2) * 64 + 32 + cseg * 8;
    signed char* tp = blob + 4096 + kw * 128 + cseg * 32;
    *(int4*)tp = make_int4(s[kw][srcbase+0], s[kw][srcbase+1], s[kw][srcbase+2], s[kw][srcbase+3]);
    *(int4*)(tp+16) = make_int4(s[kw][srcbase+4], s[kw][srcbase+5], s[kw][srcbase+6], s[kw][srcbase+7]);
}

// ======================= act quant -> A blob (swz) + At blob (transposed) =======================
__global__ void quant_act_t(const float* __restrict__ x, signed char* __restrict__ xq,
                            signed char* __restrict__ xqt, float* __restrict__ ainv,
                            int Kf, int nch) {
    __shared__ float rscale[32];
    __shared__ float rinvs[32];
    __shared__ int s[32][33];
    int t = threadIdx.x, warp = t >> 5, lane = t & 31;
    int row0 = blockIdx.x * 32;
    int mt = row0 >> 7, rbase = row0 & 127;
#pragma unroll
    for (int rr = 0; rr < 4; rr++) {
        int r = warp * 4 + rr;
        const float4* xr = (const float4*)(x + (size_t)(row0 + r) * Kf);
        float mx = 0.f;
        for (int i = lane; i < Kf / 4; i += 32) {
            float4 v = xr[i];
            mx = fmaxf(mx, fmaxf(fmaxf(fabsf(v.x), fabsf(v.y)), fmaxf(fabsf(v.z), fabsf(v.w))));
        }
#pragma unroll
        for (int o = 16; o > 0; o >>= 1) mx = fmaxf(mx, __shfl_xor_sync(0xFFFFFFFFu, mx, o));
        if (lane == 0) {
            float cm = fmaxf(mx, 1e-5f);
            rscale[r] = 127.f / cm;
            rinvs[r] = cm * (1.f / 127.f);
        }
    }
    __syncthreads();
    if (t < 32) ainv[row0 + t] = rinvs[t];
    int r = t >> 3, seg = t & 7;
    int rloc = rbase + r;
    float sc = rscale[r];
    const float* xr = x + (size_t)(row0 + r) * Kf;
    for (int kt = 0; kt < nch; kt++) {
        size_t blob = ((size_t)(mt * nch + kt)) << 14;
        int words[4];
#pragma unroll
        for (int q = 0; q < 4; q++) {
            words[q] = quant_word(*(const float4*)(xr + kt * 128 + seg * 16 + q * 4), sc, -128.f, 127.f);
            s[seg * 4 + q][r] = words[q];
        }
        *(int4*)(xq + blob + rloc * 128 + ((seg ^ (rloc & 7)) << 4)) =
            make_int4(words[0], words[1], words[2], words[3]);
        __syncthreads();
#pragma unroll
        for (int q = 0; q < 4; q++) {
            int kw = q * 8 + warp;
            *(int*)(xqt + blob + kw * 512 + (rbase + lane) * 4) = s[kw][lane];
        }
        __syncthreads();
    }
}

// ======================= rmsnorm + act quant -> hq/hqt blobs (512 threads) ===========
__global__ void rmsnorm_quant(const float* __restrict__ h, const float* __restrict__ lnw,
                              signed char* __restrict__ hq, signed char* __restrict__ hqt,
                              float* __restrict__ hinv) {
    __shared__ float sh[Idim];
    __shared__ float red[512];
    int tid = threadIdx.x;
    int row = blockIdx.x;
    int mt = row >> 7, rloc = row & 127;
    long base = (long)row * Idim;
    float ss = 0.f;
    for (int i = tid; i < Idim; i += 512) {
        float v = h[base + i];
        sh[i] = v;
        ss += v * v;
    }
    red[tid] = ss;
    __syncthreads();
    for (int o = 256; o > 0; o >>= 1) {
        if (tid < o) red[tid] += red[tid + o];
        __syncthreads();
    }
    float rs = rsqrtf(red[0] / (float)Idim + 1e-6f);
    __syncthreads();
    float mx = 0.f;
    for (int i = tid; i < Idim; i += 512) {
        float hn = lnw[i] * sh[i] * rs;
        sh[i] = hn;
        mx = fmaxf(mx, fabsf(hn));
    }
    red[tid] = mx;
    __syncthreads();
    for (int o = 256; o > 0; o >>= 1) {
        if (tid < o) red[tid] = fmaxf(red[tid], red[tid + o]);
        __syncthreads();
    }
    float cm = fmaxf(red[0], 1e-5f);
    float s = 127.f / cm;
    if (tid == 0) hinv[row] = cm * (1.f / 127.f);
    __syncthreads();
    for (int g = tid; g < Idim / 16; g += 512) {
        int kt = g >> 3, c16 = g & 7;
        size_t blob = ((size_t)(mt * NCH_I + kt)) << 14;
        int w[4];
#pragma unroll
        for (int qi = 0; qi < 4; qi++) {
            const float* p = sh + g * 16 + qi * 4;
            w[qi] = quant_word(make_float4(p[0], p[1], p[2], p[3]), s, -128.f, 127.f);
            *(int*)(hqt + blob + (c16 * 4 + qi) * 512 + rloc * 4) = w[qi];
        }
        *(int4*)(hq + blob + rloc * 128 + ((c16 ^ (rloc & 7)) << 4)) =
            make_int4(w[0], w[1], w[2], w[3]);
    }
}

// ======================= hybrid GEMM: 128x64 tile, 2 CTAs/SM, ping-pong dp4a (R15) =======
template<int NB, int STAGES>
__global__ void __launch_bounds__(256, 2)
gemm_hyb(const signed char* __restrict__ A, const signed char* __restrict__ At,
         const signed char* __restrict__ B0, const signed char* __restrict__ B1,
         float* __restrict__ C, int NC, int Nout,
         const float* __restrict__ rowinv, int iw0, int iw1)
{
    extern __shared__ char smem[];
    char* sp = (char*)(((uintptr_t)smem + 1023u) & ~(uintptr_t)1023u);
    const uint32_t db = smem_u32(sp);
    constexpr uint32_t STAGE_B = (NB == 2) ? 49152u : 40960u;
    const uint32_t mb = db + STAGES * STAGE_B;
    const int tid = threadIdx.x, lane = tid & 31, wid = tid >> 5;
    const int m0 = blockIdx.x * 128, n0 = blockIdx.y * 64;

    if (tid == 0)
        for (int s = 0; s < STAGES; s++) MBAR_INIT(mb + s * 8, 1);
    __syncthreads();

    const size_t blobA = ((size_t)blockIdx.x * NC) << 14;
    const size_t blobB = ((size_t)blockIdx.y * NC) << 13;

    auto issue = [&](int chunk) {
        if (tid != 0) return;
        int st = chunk % STAGES;
        uint32_t bar = mb + st * 8;
        uint32_t base = db + st * STAGE_B;
        MBAR_EXPECT(bar, STAGE_B);
        bulk_g2s(base,          A  + blobA + ((size_t)chunk << 14), 16384, bar);
        bulk_g2s(base + 16384,  At + blobA + ((size_t)chunk << 14), 16384, bar);
        bulk_g2s(base + 32768,  B0 + blobB + ((size_t)chunk << 13), 8192, bar);
        if (NB == 2) bulk_g2s(base + 40960, B1 + blobB + ((size_t)chunk << 13), 8192, bar);
    };

    auto swz = [](int row, int c16) -> uint32_t {
        return (uint32_t)(row * 128 + ((c16 ^ (row & 7)) << 4));
    };

    // MMA-side state (warps 4..7)
    const int wm = wid - 4;
    const int arow = (lane & 7) + ((lane & 8) ? 8 : 0);
    const int acol = (lane >> 4);
    const int brow = (lane & 7) + ((lane & 16) ? 8 : 0);
    const int bcol = ((lane >> 3) & 1);
    int acc[NB][2][4][4];
#pragma unroll
    for (int b = 0; b < NB; b++)
#pragma unroll
        for (int mt = 0; mt < 2; mt++)
#pragma unroll
            for (int n8 = 0; n8 < 4; n8++)
#pragma unroll
                for (int q = 0; q < 4; q++) acc[b][mt][n8][q] = 0;

    // dp4a-side state (warps 0..3)
    const int drow = wid * 32 + ((lane >> 3) << 3);
    const int dcol = (lane & 7) << 2;
    int dac0[8][4], dac1[8][4];
#pragma unroll
    for (int i = 0; i < 8; i++)
#pragma unroll
        for (int j = 0; j < 4; j++) { dac0[i][j] = 0; if (NB == 2) dac1[i][j] = 0; }

    int fill = 0;
    for (; fill < STAGES - 1 && fill < NC; fill++) issue(fill);

    for (int ch = 0; ch < NC; ch++) {
        if (fill < NC) { issue(fill); fill++; }
        int st = ch % STAGES;
        mbar_wait(mb + st * 8, (ch / STAGES) & 1);

        uint32_t sboff = (uint32_t)st * STAGE_B;
        if (wid >= 4) {
            uint32_t abase = db + sboff;
#pragma unroll
            for (int s = 0; s < 4; s++) {
                uint32_t af[2][4];
#pragma unroll
                for (int mt = 0; mt < 2; mt++) {
                    int row = wm * 32 + mt * 16 + arow;
                    LDSM4(af[mt], abase + swz(row, s * 2 + acol));
                }
#pragma unroll
                for (int b = 0; b < NB; b++) {
                    uint32_t bb = abase + 32768u + (uint32_t)b * 8192u;
#pragma unroll
                    for (int nt = 0; nt < 2; nt++) {
                        uint32_t bf[4];
                        int row = nt * 16 + brow;
                        LDSM4(bf, bb + swz(row, s * 2 + bcol));
#pragma unroll
                        for (int mt = 0; mt < 2; mt++) {
                            MMA_S8(acc[b][mt][nt * 2 + 0], af[mt], bf[0], bf[1]);
                            MMA_S8(acc[b][mt][nt * 2 + 1], af[mt], bf[2], bf[3]);
                        }
                    }
                }
            }
        } else {
            // --- ping-pong dp4a: two-deep register buffers indexed by kk&1 (no copy MOVs) ---
            uint32_t at  = db + sboff + 16384u + (uint32_t)(drow * 4);
            uint32_t bt0 = db + sboff + 32768u + 4096u + (uint32_t)(dcol * 4);
            uint32_t bt1 = db + sboff + 40960u + 4096u + (uint32_t)(dcol * 4);
            int4 a0b[2], a1b[2], b0b[2], b1b[2];
            LDS128(a0b[0], at); LDS128(a1b[0], at + 16);
            LDS128(b0b[0], bt0);
            if (NB == 2) LDS128(b1b[0], bt1);
#pragma unroll 8
            for (int kk = 0; kk < 32; kk++) {
                const int cur = kk & 1, nxt = cur ^ 1;
                if (kk < 31) {
                    LDS128(a0b[nxt], at + (kk + 1) * 512);
                    LDS128(a1b[nxt], at + (kk + 1) * 512 + 16);
                    LDS128(b0b[nxt], bt0 + (kk + 1) * 128);
                    if (NB == 2) LDS128(b1b[nxt], bt1 + (kk + 1) * 128);
                }
                int a[8] = {a0b[cur].x, a0b[cur].y, a0b[cur].z, a0b[cur].w,
                            a1b[cur].x, a1b[cur].y, a1b[cur].z, a1b[cur].w};
                int b0w[4] = {b0b[cur].x, b0b[cur].y, b0b[cur].z, b0b[cur].w};
#pragma unroll
                for (int i = 0; i < 8; i++)
#pragma unroll
                    for (int j = 0; j < 4; j++)
                        dac0[i][j] = __dp4a(a[i], b0w[j], dac0[i][j]);
                if (NB == 2) {
                    int b1w[4] = {b1b[cur].x, b1b[cur].y, b1b[cur].z, b1b[cur].w};
#pragma unroll
                    for (int i = 0; i < 8; i++)
#pragma unroll
                        for (int j = 0; j < 4; j++)
                            dac1[i][j] = __dp4a(a[i], b1w[j], dac1[i][j]);
                }
            }
        }
        __syncthreads();
    }

    // ======== epilogue ========
    float wg0 = g_winv[iw0], wu0 = (NB == 2) ? g_winv[iw1] : 0.f;
    if (wid >= 4) {
#pragma unroll
        for (int mt = 0; mt < 2; mt++) {
            int r = m0 + wm * 32 + mt * 16 + (lane >> 2);
            float ai0 = rowinv[r], ai1 = rowinv[r + 8];
            float* crow0 = C + (size_t)r * Nout;
            float* crow1 = C + (size_t)(r + 8) * Nout;
            if (NB == 2) {
                float sg0 = ai0 * wg0, su0 = ai0 * wu0;
                float sg1 = ai1 * wg0, su1 = ai1 * wu0;
#pragma unroll
                for (int n8 = 0; n8 < 4; n8++) {
                    int c = n0 + n8 * 8 + (lane & 3) * 2;
                    float g00 = (float)acc[0][mt][n8][0] * sg0;
                    float g01 = (float)acc[0][mt][n8][1] * sg0;
                    float g10 = (float)acc[0][mt][n8][2] * sg1;
                    float g11 = (float)acc[0][mt][n8][3] * sg1;
                    float u00 = (float)acc[1][mt][n8][0] * su0;
                    float u01 = (float)acc[1][mt][n8][1] * su0;
                    float u10 = (float)acc[1][mt][n8][2] * su1;
                    float u11 = (float)acc[1][mt][n8][3] * su1;
                    float2 o0, o1;
                    o0.x = (g00 / (1.f + __expf(-g00))) * u00;
                    o0.y = (g01 / (1.f + __expf(-g01))) * u01;
                    o1.x = (g10 / (1.f + __expf(-g10))) * u10;
                    o1.y = (g11 / (1.f + __expf(-g11))) * u11;
                    *(float2*)(crow0 + c) = o0;
                    *(float2*)(crow1 + c) = o1;
                }
            } else {
                float s0 = ai0 * wg0, s1 = ai1 * wg0;
#pragma unroll
                for (int n8 = 0; n8 < 4; n8++) {
                    int c = n0 + n8 * 8 + (lane & 3) * 2;
                    float2 o0, o1;
                    o0.x = (float)acc[0][mt][n8][0] * s0;
                    o0.y = (float)acc[0][mt][n8][1] * s0;
                    o1.x = (float)acc[0][mt][n8][2] * s1;
                    o1.y = (float)acc[0][mt][n8][3] * s1;
                    *(float2*)(crow0 + c) = o0;
                    *(float2*)(crow1 + c) = o1;
                }
            }
        }
    } else {
        int cbase = n0 + 32 + dcol;
#pragma unroll
        for (int i = 0; i < 8; i++) {
            int r = m0 + drow + i;
            float ai = rowinv[r];
            float* crow = C + (size_t)r * Nout + cbase;
            if (NB == 2) {
                float sg = ai * wg0, su = ai * wu0;
                float4 o;
                float g0 = (float)dac0[i][0] * sg, u0 = (float)dac1[i][0] * su;
                float g1 = (float)dac0[i][1] * sg, u1 = (float)dac1[i][1] * su;
                float g2 = (float)dac0[i][2] * sg, u2 = (float)dac1[i][2] * su;
                float g3 = (float)dac0[i][3] * sg, u3 = (float)dac1[i][3] * su;
                o.x = (g0 / (1.f + __expf(-g0))) * u0;
                o.y = (g1 / (1.f + __expf(-g1))) * u1;
                o.z = (g2 / (1.f + __expf(-g2))) * u2;
                o.w = (g3 / (1.f + __expf(-g3))) * u3;
                *(float4*)crow = o;
            } else {
                float sc = ai * wg0;
                float4 o;
                o.x = (float)dac0[i][0] * sc;
                o.y = (float)dac0[i][1] * sc;
                o.z = (float)dac0[i][2] * sc;
                o.w = (float)dac0[i][3] * sc;
                *(float4*)crow = o;
            }
        }
    }
}

// ======================= launch =======================
extern "C" void kernel_launch(void* const* d_in, const int* in_sizes, int n_in,
                              void* d_out, int out_size) {
    const float* x   = (const float*)d_in[0];
    const float* wg  = (const float*)d_in[1];
    const float* wu  = (const float*)d_in[2];
    const float* wd  = (const float*)d_in[3];
    const float* lnw = (const float*)d_in[4];
    float* out = (float*)d_out;

    signed char *wqg, *wqu, *wqd, *xq, *xqt, *hq, *hqt;
    float *gbuf, *ainv, *hinv;
    cudaGetSymbolAddress((void**)&wqg, g_wqg);
    cudaGetSymbolAddress((void**)&wqu, g_wqu);
    cudaGetSymbolAddress((void**)&wqd, g_wqd);
    cudaGetSymbolAddress((void**)&xq, g_xq);
    cudaGetSymbolAddress((void**)&xqt, g_xqt);
    cudaGetSymbolAddress((void**)&hq, g_hq);
    cudaGetSymbolAddress((void**)&hqt, g_hqt);
    cudaGetSymbolAddress((void**)&gbuf, g_gbuf);
    cudaGetSymbolAddress((void**)&ainv, g_ainv);
    cudaGetSymbolAddress((void**)&hinv, g_hinv);

    const int SMEM2 = 2 * 49152 + 1024 + 64;   // 2 CTAs/SM
    const int SMEM1 = 2 * 40960 + 1024 + 64;   // 2 CTAs/SM
    cudaFuncSetAttribute(gemm_hyb<2, 2>, cudaFuncAttributeMaxDynamicSharedMemorySize, SMEM2);
    cudaFuncSetAttribute(gemm_hyb<1, 2>, cudaFuncAttributeMaxDynamicSharedMemorySize, SMEM1);

    const long NWl = (long)NW;

    absmean_all<<<dim3(2048, 3), 256>>>(wg, wu, wd, NWl);
    quant_weight_all<<<dim3(2752, 3), 256>>>(wg, wu, wd);
    quant_act_t<<<Tdim / 32, 256>>>(x, xq, xqt, ainv, Hdim, NCH_H);
    // ncu slot: fused gate+up hybrid GEMM -> h = silu(g)*u
    gemm_hyb<2, 2><<<dim3(Tdim / 128, Idim / 64), 256, SMEM2>>>(
        xq, xqt, wqg, wqu, gbuf, NCH_H, Idim, ainv, 0, 1);
    rmsnorm_quant<<<Tdim, 512>>>(gbuf, lnw, hq, hqt, hinv);
    gemm_hyb<1, 2><<<dim3(Tdim / 128, Hdim / 64), 256, SMEM1>>>(
        hq, hqt, wqd, wqd, out, NCH_I, Hdim, hinv, 2, 2);
}